// round 13
// baseline (speedup 1.0000x reference)
#include <cuda_runtime.h>
#include <math.h>
#include <cstdint>

#define BB 64
#define PP 8732
#define CC 81
#define TPB 256
#define TILE 32
#define TX   273                        // tiles per batch row (272 full + 28)
#define NTILES (TX * BB)                // 17472
#define NPB 592                         // persistent blocks (4/SM x 148)
#define NBUF 4

// ---- per-buffer float offsets (byte offsets %16 == 0) ----
#define BUF_SZ  3392                    // floats (13568 B)
#define B_CONF  0                       // 32*81 = 2592
#define B_LOC   2592                    // 128
#define B_LOCT  2720                    // 128
#define B_FC    2848                    // 256
#define B_FCT   3104                    // 256
#define B_T     3360                    // 32 ints
// ---- aux (float offsets) ----
#define OFF_MBAR (NBUF * BUF_SZ)        // 13568: 4 x u64 (byte 54272, 16B aligned)
#define OFF_PS   (OFF_MBAR + 8)         // 256 partials
#define OFF_ISL  (OFF_PS + 256)
#define OFF_NFB  (OFF_ISL + 1)
#define OFF_FBR  (OFF_NFB + 1)          // 64
#define OFF_FIN  (OFF_FBR + 66)         // pad to 8B alignment; 4 doubles
#define SMEM_FLOATS (OFF_FIN + 8)
#define SMEM_BYTES  (SMEM_FLOATS * 4)   // ~55.4 KB

// ---- device scratch (zero at load; self-reset after every launch) ----
__device__ double d_loss_l, d_loss_fc;
__device__ double d_ce_all[BB], d_ce_pos[BB];
__device__ int    d_numpos[BB];
__device__ double d_rowC[BB];
__device__ float  d_ce_row[PP];
__device__ int    d_done;

__device__ __forceinline__ uint32_t smem_u32(const void* p) {
    uint32_t a;
    asm("{ .reg .u64 t; cvta.to.shared.u64 t, %1; cvt.u32.u64 %0, t; }" : "=r"(a) : "l"(p));
    return a;
}
__device__ __forceinline__ void mbar_init(uint32_t a, uint32_t n) {
    asm volatile("mbarrier.init.shared.b64 [%0], %1;" :: "r"(a), "r"(n) : "memory");
}
__device__ __forceinline__ void mbar_expect(uint32_t a, uint32_t tx) {
    asm volatile("mbarrier.arrive.expect_tx.shared.b64 _, [%0], %1;" :: "r"(a), "r"(tx) : "memory");
}
__device__ __forceinline__ void mbar_wait(uint32_t a, uint32_t par) {
    asm volatile(
        "{\n\t.reg .pred P;\n\t"
        "WL_%=:\n\t"
        "mbarrier.try_wait.parity.acquire.cta.shared::cta.b64 P, [%0], %1, 0x989680;\n\t"
        "@P bra WD_%=;\n\t"
        "bra WL_%=;\n\t"
        "WD_%=:\n\t}"
        :: "r"(a), "r"(par) : "memory");
}
__device__ __forceinline__ void bulk_g2s(uint32_t dst, const void* src, uint32_t bytes, uint32_t mbar) {
    asm volatile(
        "cp.async.bulk.shared::cta.global.mbarrier::complete_tx::bytes [%0], [%1], %2, [%3];"
        :: "r"(dst), "l"(src), "r"(bytes), "r"(mbar) : "memory");
}

// tid0 only: arm mbarrier + issue 6 bulk copies for one tile.
__device__ __forceinline__ void arm_tile(
    uint32_t smb, int buf, int tile, uint32_t mbar,
    const float* loc_data, const float* conf, const float* fc_data,
    const float* loc_t, const float* fc_t, const int* conf_t)
{
    if (tile >= NTILES) return;
    const int b  = tile / TX;
    const int p0 = (tile - b * TX) * TILE;
    const int nloc = (PP - p0 < TILE) ? (PP - p0) : TILE;    // 32 or 28 (%4==0)
    const unsigned rowp = (unsigned)(b * PP + p0);
    const uint32_t base = smb + (uint32_t)(buf * BUF_SZ) * 4u;
    mbar_expect(mbar, (uint32_t)nloc * 424u);
    bulk_g2s(base + B_CONF * 4, conf + rowp * (unsigned)CC, (uint32_t)nloc * 324u, mbar);
    bulk_g2s(base + B_LOC  * 4, loc_data + rowp * 4u,       (uint32_t)nloc * 16u,  mbar);
    bulk_g2s(base + B_LOCT * 4, loc_t    + rowp * 4u,       (uint32_t)nloc * 16u,  mbar);
    bulk_g2s(base + B_FC   * 4, fc_data  + rowp * 8u,       (uint32_t)nloc * 32u,  mbar);
    bulk_g2s(base + B_FCT  * 4, fc_t     + rowp * 8u,       (uint32_t)nloc * 32u,  mbar);
    bulk_g2s(base + B_T    * 4, conf_t   + rowp,            (uint32_t)nloc * 4u,   mbar);
}

__global__ __launch_bounds__(TPB) void k_fused(
    const float* __restrict__ loc_data, const float* __restrict__ conf,
    const float* __restrict__ fc_data,  const float* __restrict__ loc_t,
    const float* __restrict__ fc_t,     const int* __restrict__ conf_t,
    float* __restrict__ out)
{
    extern __shared__ float sm[];
    const uint32_t smb = smem_u32(sm);
    const int tid  = threadIdx.x;
    const int lane = tid & 31;
    const int warp = tid >> 5;
    const int bid  = blockIdx.x;
    const uint32_t mb = smb + OFF_MBAR * 4;

    if (tid == 0) {
        #pragma unroll
        for (int i = 0; i < NBUF; ++i) mbar_init(mb + i * 8, 1);
    }
    __syncthreads();

    float accL = 0.f, accF = 0.f;

    // prologue: arm 3 tiles ahead
    if (tid == 0) {
        arm_tile(smb, 0, bid,           mb,      loc_data, conf, fc_data, loc_t, fc_t, conf_t);
        arm_tile(smb, 1, bid + NPB,     mb + 8,  loc_data, conf, fc_data, loc_t, fc_t, conf_t);
        arm_tile(smb, 2, bid + 2 * NPB, mb + 16, loc_data, conf, fc_data, loc_t, fc_t, conf_t);
    }

    int k = 0;
    for (int tile = bid; tile < NTILES; tile += NPB, ++k) {
        const int buf  = k & 3;
        const int base = buf * BUF_SZ;
        const int b    = tile / TX;
        const int p0   = (tile - b * TX) * TILE;
        const int nloc = (PP - p0 < TILE) ? (PP - p0) : TILE;

        // refill the buffer freed last iteration with tile k+3 (depth-3 prefetch)
        if (tid == 0)
            arm_tile(smb, (k + 3) & 3, tile + 3 * NPB, mb + ((k + 3) & 3) * 8,
                     loc_data, conf, fc_data, loc_t, fc_t, conf_t);

        mbar_wait(mb + buf * 8, (k >> 2) & 1);

        // phase A: 8 threads per prior, exp-sum segments of 10 (q==7 gets 11)
        {
            const int prior = tid & 31;
            const int q     = tid >> 5;
            float part = 0.f;
            if (prior < nloc) {
                const float* row = sm + base + B_CONF + prior * CC + q * 10;
                float a0 = 0.f, a1 = 0.f;
                #pragma unroll
                for (int c = 0; c < 10; c += 2) {
                    a0 += __expf(row[c]);
                    a1 += __expf(row[c + 1]);
                }
                if (q == 7) a0 += __expf(row[10]);       // element 80
                part = a0 + a1;
            }
            sm[OFF_PS + tid] = part;
        }
        __syncthreads();

        // phase B (warp 0): per-prior ce + loc/fc + row atomics
        if (warp == 0) {
            float ces = 0.f, cep = 0.f;
            int   np = 0;
            if (lane < nloc) {
                float S = 0.f;
                #pragma unroll
                for (int q = 0; q < 8; ++q) S += sm[OFF_PS + lane + 32 * q];
                int t = ((int*)(sm + base + B_T))[lane];
                float ce = __logf(S) - sm[base + B_CONF + lane * CC + t];
                ces = ce;
                if (t > 0) {
                    cep = ce; np = 1;
                    float4 a0 = ((float4*)(sm + base + B_LOC))[lane];
                    float4 t0 = ((float4*)(sm + base + B_LOCT))[lane];
                    float4 b0 = ((float4*)(sm + base + B_FC))[lane * 2];
                    float4 u0 = ((float4*)(sm + base + B_FCT))[lane * 2];
                    float4 b1 = ((float4*)(sm + base + B_FC))[lane * 2 + 1];
                    float4 u1 = ((float4*)(sm + base + B_FCT))[lane * 2 + 1];
                    float d;
                    d = fabsf(a0.x - t0.x); accL += (d < 1.f) ? 0.5f*d*d : d - 0.5f;
                    d = fabsf(a0.y - t0.y); accL += (d < 1.f) ? 0.5f*d*d : d - 0.5f;
                    d = fabsf(a0.z - t0.z); accL += (d < 1.f) ? 0.5f*d*d : d - 0.5f;
                    d = fabsf(a0.w - t0.w); accL += (d < 1.f) ? 0.5f*d*d : d - 0.5f;
                    d = fabsf(b0.x - u0.x); accF += (d < 1.f) ? 0.5f*d*d : d - 0.5f;
                    d = fabsf(b0.y - u0.y); accF += (d < 1.f) ? 0.5f*d*d : d - 0.5f;
                    d = fabsf(b0.z - u0.z); accF += (d < 1.f) ? 0.5f*d*d : d - 0.5f;
                    d = fabsf(b0.w - u0.w); accF += (d < 1.f) ? 0.5f*d*d : d - 0.5f;
                    d = fabsf(b1.x - u1.x); accF += (d < 1.f) ? 0.5f*d*d : d - 0.5f;
                    d = fabsf(b1.y - u1.y); accF += (d < 1.f) ? 0.5f*d*d : d - 0.5f;
                    d = fabsf(b1.z - u1.z); accF += (d < 1.f) ? 0.5f*d*d : d - 0.5f;
                    d = fabsf(b1.w - u1.w); accF += (d < 1.f) ? 0.5f*d*d : d - 0.5f;
                }
            }
            #pragma unroll
            for (int o = 16; o; o >>= 1) {
                ces += __shfl_xor_sync(0xffffffffu, ces, o);
                cep += __shfl_xor_sync(0xffffffffu, cep, o);
                np  += __shfl_xor_sync(0xffffffffu, np,  o);
            }
            if (lane == 0) {
                atomicAdd(&d_ce_all[b], (double)ces);
                atomicAdd(&d_ce_pos[b], (double)cep);
                atomicAdd(&d_numpos[b], np);
            }
        }
        __syncthreads();                 // buffer consumed; free for next arm
    }

    // flush loc/fc accumulators (nonzero only in warp 0)
    if (warp == 0) {
        #pragma unroll
        for (int o = 16; o; o >>= 1) {
            accL += __shfl_xor_sync(0xffffffffu, accL, o);
            accF += __shfl_xor_sync(0xffffffffu, accF, o);
        }
        if (lane == 0) {
            atomicAdd(&d_loss_l,  (double)accL);
            atomicAdd(&d_loss_fc, (double)accF);
        }
    }

    // ---- completion handshake: last block does mining + finalize + reset ----
    int* s_isl = (int*)(sm + OFF_ISL);
    __threadfence();
    __syncthreads();
    if (tid == 0) *s_isl = (atomicAdd(&d_done, 1) == NPB - 1);
    __syncthreads();
    if (!*s_isl) return;
    __threadfence();

    int*    sh    = (int*)sm;            // overlay on drained buffers
    double* shd   = (double*)(sm + 256);
    int*    s_nfb = (int*)(sm + OFF_NFB);
    int*    s_fbr = (int*)(sm + OFF_FBR);
    double* s_fin = (double*)(sm + OFF_FIN);

    // per-row selection. fast path: num_neg >= #negatives -> row sum = all ce.
    if (tid == 0) *s_nfb = 0;
    __syncthreads();
    if (tid < BB) {
        int npb = d_numpos[tid];
        long k3 = 3L * (long)npb;
        int kk = (k3 < (long)(PP - 1)) ? (int)k3 : (PP - 1);
        int nneg = PP - npb;
        if (kk >= nneg)     d_rowC[tid] = d_ce_all[tid];
        else if (kk <= 0)   d_rowC[tid] = d_ce_pos[tid];
        else { int s = atomicAdd(s_nfb, 1); s_fbr[s] = tid; }
    }
    __syncthreads();

    // exact fallback (never triggered on this data): recompute ce for the row,
    // then bit-bisection for the k-th largest negative ce.
    const int nfbv = *s_nfb;
    for (int fi = 0; fi < nfbv; ++fi) {
        int bb = s_fbr[fi];
        long rb = (long)bb * PP;
        for (int i = warp; i < PP; i += 8) {
            const long cb = (rb + i) * CC;
            float v0 = conf[cb + lane];
            float v1 = conf[cb + lane + 32];
            float v2 = (lane < CC - 64) ? conf[cb + lane + 64] : 0.f;
            float s = __expf(v0) + __expf(v1);
            if (lane < CC - 64) s += __expf(v2);
            #pragma unroll
            for (int o = 16; o; o >>= 1) s += __shfl_xor_sync(0xffffffffu, s, o);
            int t = conf_t[rb + i];
            float cand = (t < 32) ? v0 : (t < 64) ? v1 : v2;
            float gath = __shfl_sync(0xffffffffu, cand, t & 31);
            if (lane == 0) d_ce_row[i] = __logf(s) - gath;
        }
        __syncthreads();
        int npb = d_numpos[bb];
        long k3 = 3L * (long)npb;
        int kk = (k3 < (long)(PP - 1)) ? (int)k3 : (PP - 1);
        unsigned lo = 0u, hi = 0x7f800000u;
        while (lo < hi) {
            unsigned mid = lo + (hi - lo + 1u) / 2u;
            int c = 0;
            for (int i = tid; i < PP; i += TPB)
                if (conf_t[rb + i] == 0 &&
                    __float_as_uint(fmaxf(d_ce_row[i], 0.f)) >= mid) c++;
            sh[tid] = c; __syncthreads();
            for (int s = TPB/2; s; s >>= 1) { if (tid < s) sh[tid] += sh[tid + s]; __syncthreads(); }
            int tot = sh[0]; __syncthreads();
            if (tot >= kk) lo = mid; else hi = mid - 1u;
        }
        int c = 0; double su = 0.0;
        for (int i = tid; i < PP; i += TPB) {
            if (conf_t[rb + i] == 0) {
                float v = d_ce_row[i];
                if (__float_as_uint(fmaxf(v, 0.f)) > lo) { c++; su += (double)v; }
            }
        }
        sh[tid] = c; shd[tid] = su; __syncthreads();
        for (int s = TPB/2; s; s >>= 1) {
            if (tid < s) { sh[tid] += sh[tid + s]; shd[tid] += shd[tid + s]; }
            __syncthreads();
        }
        if (tid == 0)
            d_rowC[bb] = d_ce_pos[bb] + shd[0] + (double)(kk - sh[0]) * (double)__uint_as_float(lo);
        __syncthreads();
    }

    // ---- finalize (parallel) ----
    double n = (tid < BB) ? (double)d_numpos[tid] : 0.0;
    double c = (tid < BB) ? d_rowC[tid] : 0.0;
    if (tid < 64) {
        #pragma unroll
        for (int o = 16; o; o >>= 1) {
            n += __shfl_xor_sync(0xffffffffu, n, o);
            c += __shfl_xor_sync(0xffffffffu, c, o);
        }
        if (lane == 0) { s_fin[(tid >> 5) * 2] = n; s_fin[(tid >> 5) * 2 + 1] = c; }
    }
    __syncthreads();
    if (tid == 0) {
        double N  = s_fin[0] + s_fin[2];
        double Cc = s_fin[1] + s_fin[3];
        out[0] = (float)(d_loss_l / N);
        out[1] = (float)(Cc / N);
        out[2] = (float)(d_loss_fc / N);
    }

    // ---- self-reset device state for the next (graph-replayed) launch ----
    __syncthreads();
    if (tid < BB) {
        d_ce_all[tid] = 0.0; d_ce_pos[tid] = 0.0;
        d_numpos[tid] = 0;   d_rowC[tid]   = 0.0;
    }
    if (tid == 0) { d_loss_l = 0.0; d_loss_fc = 0.0; d_done = 0; }
}

extern "C" void kernel_launch(void* const* d_in, const int* in_sizes, int n_in,
                              void* d_out, int out_size) {
    const float* loc_data = (const float*)d_in[0];
    const float* conf     = (const float*)d_in[1];
    const float* fc_data  = (const float*)d_in[2];
    const float* loc_t    = (const float*)d_in[3];
    const float* fc_t     = (const float*)d_in[4];
    const int*   conf_t   = (const int*)d_in[5];

    cudaFuncSetAttribute(k_fused, cudaFuncAttributeMaxDynamicSharedMemorySize, SMEM_BYTES);
    k_fused<<<NPB, TPB, SMEM_BYTES>>>(loc_data, conf, fc_data, loc_t, fc_t, conf_t, (float*)d_out);
}

// round 14
// speedup vs baseline: 1.1054x; 1.1054x over previous
#include <cuda_runtime.h>
#include <math.h>
#include <cstdint>

#define BB 64
#define PP 8732
#define CC 81
#define TPB 256
#define TILE 64
#define TX   137                        // tiles per batch row
#define NTILES (TX * BB)                // 8768
#define NPB 592                         // persistent blocks (4/SM x 148)

// ---- per-buffer float offsets (all byte offsets %16 == 0) ----
#define BUF_SZ  6784                    // floats (27136 B)
#define B_CONF  0                       // 64*81 = 5184
#define B_LOC   5184                    // 256
#define B_LOCT  5440                    // 256
#define B_FC    5696                    // 512
#define B_FCT   6208                    // 512
#define B_T     6720                    // 64 ints
// ---- aux (float offsets) ----
#define OFF_MBAR 13568                  // 2 x u64 mbarrier (byte 54272, 16B aligned)
#define OFF_PS   13572                  // 256 partials
#define OFF_RC   13828                  // 2
#define OFF_RP   13830                  // 2
#define OFF_RN   13832                  // 2 ints
#define OFF_RL   13834                  // 8
#define OFF_RF   13842                  // 8
#define OFF_ISL  13850
#define OFF_NFB  13851
#define OFF_FBR  13852                  // 64
#define OFF_FIN  13916                  // 4 doubles (byte 55664, 8B aligned)
#define SMEM_FLOATS 13924
#define SMEM_BYTES  (SMEM_FLOATS * 4)   // 55696

// ---- device scratch (zero at load; self-reset at end of every launch) ----
__device__ double d_loss_l, d_loss_fc;
__device__ double d_ce_all[BB], d_ce_pos[BB];
__device__ int    d_numpos[BB];
__device__ double d_rowC[BB];
__device__ float  d_ce_row[PP];
__device__ int    d_done;

__device__ __forceinline__ uint32_t smem_u32(const void* p) {
    uint32_t a;
    asm("{ .reg .u64 t; cvta.to.shared.u64 t, %1; cvt.u32.u64 %0, t; }" : "=r"(a) : "l"(p));
    return a;
}
__device__ __forceinline__ void mbar_init(uint32_t a, uint32_t n) {
    asm volatile("mbarrier.init.shared.b64 [%0], %1;" :: "r"(a), "r"(n) : "memory");
}
__device__ __forceinline__ void mbar_expect(uint32_t a, uint32_t tx) {
    asm volatile("mbarrier.arrive.expect_tx.shared.b64 _, [%0], %1;" :: "r"(a), "r"(tx) : "memory");
}
__device__ __forceinline__ void mbar_wait(uint32_t a, uint32_t par) {
    asm volatile(
        "{\n\t.reg .pred P;\n\t"
        "WL_%=:\n\t"
        "mbarrier.try_wait.parity.acquire.cta.shared::cta.b64 P, [%0], %1, 0x989680;\n\t"
        "@P bra WD_%=;\n\t"
        "bra WL_%=;\n\t"
        "WD_%=:\n\t}"
        :: "r"(a), "r"(par) : "memory");
}
__device__ __forceinline__ void bulk_g2s(uint32_t dst, const void* src, uint32_t bytes, uint32_t mbar) {
    asm volatile(
        "cp.async.bulk.shared::cta.global.mbarrier::complete_tx::bytes [%0], [%1], %2, [%3];"
        :: "r"(dst), "l"(src), "r"(bytes), "r"(mbar) : "memory");
}

// tid0 only: arm mbarrier + issue 6 bulk copies for one tile.
__device__ __forceinline__ void arm_tile(
    uint32_t smb, int buf, int tile, uint32_t mbar,
    const float* loc_data, const float* conf, const float* fc_data,
    const float* loc_t, const float* fc_t, const int* conf_t)
{
    if (tile >= NTILES) return;
    const int b  = tile / TX;
    const int p0 = (tile - b * TX) * TILE;
    const int nloc = (PP - p0 < TILE) ? (PP - p0) : TILE;    // 64 or 28
    const unsigned rowp = (unsigned)(b * PP + p0);           // %4 == 0
    const uint32_t base = smb + (uint32_t)(buf * BUF_SZ) * 4u;
    mbar_expect(mbar, (uint32_t)nloc * 424u);
    bulk_g2s(base + B_CONF * 4, conf + rowp * (unsigned)CC, (uint32_t)nloc * 324u, mbar);
    bulk_g2s(base + B_LOC  * 4, loc_data + rowp * 4u,       (uint32_t)nloc * 16u,  mbar);
    bulk_g2s(base + B_LOCT * 4, loc_t    + rowp * 4u,       (uint32_t)nloc * 16u,  mbar);
    bulk_g2s(base + B_FC   * 4, fc_data  + rowp * 8u,       (uint32_t)nloc * 32u,  mbar);
    bulk_g2s(base + B_FCT  * 4, fc_t     + rowp * 8u,       (uint32_t)nloc * 32u,  mbar);
    bulk_g2s(base + B_T    * 4, conf_t   + rowp,            (uint32_t)nloc * 4u,   mbar);
}

__global__ __launch_bounds__(TPB) void k_fused(
    const float* __restrict__ loc_data, const float* __restrict__ conf,
    const float* __restrict__ fc_data,  const float* __restrict__ loc_t,
    const float* __restrict__ fc_t,     const int* __restrict__ conf_t,
    float* __restrict__ out)
{
    extern __shared__ float sm[];
    const uint32_t smb = smem_u32(sm);
    const int tid  = threadIdx.x;
    const int lane = tid & 31;
    const int warp = tid >> 5;
    const int bid  = blockIdx.x;
    const uint32_t mb0 = smb + OFF_MBAR * 4;
    const uint32_t mb1 = mb0 + 8;

    if (tid == 0) { mbar_init(mb0, 1); mbar_init(mb1, 1); }
    __syncthreads();

    float accL = 0.f, accF = 0.f;

    if (tid == 0) {
        arm_tile(smb, 0, bid,       mb0, loc_data, conf, fc_data, loc_t, fc_t, conf_t);
        arm_tile(smb, 1, bid + NPB, mb1, loc_data, conf, fc_data, loc_t, fc_t, conf_t);
    }

    int ph0 = 0, ph1 = 0, cur = 0;
    for (int tile = bid; tile < NTILES; tile += NPB) {
        const int base = cur ? BUF_SZ : 0;
        const int b    = tile / TX;
        const int p0   = (tile - b * TX) * TILE;
        const int nloc = (PP - p0 < TILE) ? (PP - p0) : TILE;

        // wait for this buffer's TMA completion (parity per buffer)
        if (cur) { mbar_wait(mb1, ph1); ph1 ^= 1; }
        else     { mbar_wait(mb0, ph0); ph0 ^= 1; }

        // phase A: 4 threads per prior, exp-sum segments 20/20/20/21
        {
            const int prior = tid & 63;
            const int q     = tid >> 6;
            float part = 0.f;
            if (prior < nloc) {
                const float* row = sm + base + B_CONF + prior * CC + q * 20;
                float a0 = 0.f, a1 = 0.f;
                #pragma unroll
                for (int c = 0; c < 20; c += 2) {
                    a0 += __expf(row[c]);
                    a1 += __expf(row[c + 1]);
                }
                if (q == 3) a0 += __expf(row[20]);       // element 80
                part = a0 + a1;
            }
            sm[OFF_PS + tid] = part;
        }
        __syncthreads();

        // phase B: per-prior ce + loc/fc (threads 0..63)
        float ces = 0.f, cep = 0.f;
        int   np = 0;
        if (tid < nloc) {
            float S = (sm[OFF_PS + tid] + sm[OFF_PS + 64 + tid])
                    + (sm[OFF_PS + 128 + tid] + sm[OFF_PS + 192 + tid]);
            int t = ((int*)(sm + base + B_T))[tid];
            float ce = __logf(S) - sm[base + B_CONF + tid * CC + t];
            ces = ce;
            if (t > 0) {
                cep = ce; np = 1;
                float4 a0 = ((float4*)(sm + base + B_LOC))[tid];
                float4 t0 = ((float4*)(sm + base + B_LOCT))[tid];
                float4 b0 = ((float4*)(sm + base + B_FC))[tid * 2];
                float4 u0 = ((float4*)(sm + base + B_FCT))[tid * 2];
                float4 b1 = ((float4*)(sm + base + B_FC))[tid * 2 + 1];
                float4 u1 = ((float4*)(sm + base + B_FCT))[tid * 2 + 1];
                float d;
                d = fabsf(a0.x - t0.x); accL += (d < 1.f) ? 0.5f*d*d : d - 0.5f;
                d = fabsf(a0.y - t0.y); accL += (d < 1.f) ? 0.5f*d*d : d - 0.5f;
                d = fabsf(a0.z - t0.z); accL += (d < 1.f) ? 0.5f*d*d : d - 0.5f;
                d = fabsf(a0.w - t0.w); accL += (d < 1.f) ? 0.5f*d*d : d - 0.5f;
                d = fabsf(b0.x - u0.x); accF += (d < 1.f) ? 0.5f*d*d : d - 0.5f;
                d = fabsf(b0.y - u0.y); accF += (d < 1.f) ? 0.5f*d*d : d - 0.5f;
                d = fabsf(b0.z - u0.z); accF += (d < 1.f) ? 0.5f*d*d : d - 0.5f;
                d = fabsf(b0.w - u0.w); accF += (d < 1.f) ? 0.5f*d*d : d - 0.5f;
                d = fabsf(b1.x - u1.x); accF += (d < 1.f) ? 0.5f*d*d : d - 0.5f;
                d = fabsf(b1.y - u1.y); accF += (d < 1.f) ? 0.5f*d*d : d - 0.5f;
                d = fabsf(b1.z - u1.z); accF += (d < 1.f) ? 0.5f*d*d : d - 0.5f;
                d = fabsf(b1.w - u1.w); accF += (d < 1.f) ? 0.5f*d*d : d - 0.5f;
            }
        }
        if (warp < 2) {
            #pragma unroll
            for (int o = 16; o; o >>= 1) {
                ces += __shfl_xor_sync(0xffffffffu, ces, o);
                cep += __shfl_xor_sync(0xffffffffu, cep, o);
                np  += __shfl_xor_sync(0xffffffffu, np,  o);
            }
            if (lane == 0) {
                sm[OFF_RC + warp] = ces; sm[OFF_RP + warp] = cep;
                ((int*)(sm + OFF_RN))[warp] = np;
            }
        }
        __syncthreads();                 // buffer + aux consumed; safe to refill
        if (tid == 0) {
            atomicAdd(&d_ce_all[b], (double)(sm[OFF_RC] + sm[OFF_RC + 1]));
            atomicAdd(&d_ce_pos[b], (double)(sm[OFF_RP] + sm[OFF_RP + 1]));
            atomicAdd(&d_numpos[b], ((int*)(sm + OFF_RN))[0] + ((int*)(sm + OFF_RN))[1]);
            arm_tile(smb, cur, tile + 2 * NPB, cur ? mb1 : mb0,
                     loc_data, conf, fc_data, loc_t, fc_t, conf_t);
        }
        cur ^= 1;
    }

    // flush register accumulators
    #pragma unroll
    for (int o = 16; o; o >>= 1) {
        accL += __shfl_xor_sync(0xffffffffu, accL, o);
        accF += __shfl_xor_sync(0xffffffffu, accF, o);
    }
    if (lane == 0) { sm[OFF_RL + warp] = accL; sm[OFF_RF + warp] = accF; }
    __syncthreads();
    if (tid == 0) {
        float L = 0.f, F = 0.f;
        #pragma unroll
        for (int w = 0; w < 8; ++w) { L += sm[OFF_RL + w]; F += sm[OFF_RF + w]; }
        atomicAdd(&d_loss_l,  (double)L);
        atomicAdd(&d_loss_fc, (double)F);
    }

    // ---- completion handshake: last block does mining + finalize + reset ----
    int* s_isl = (int*)(sm + OFF_ISL);
    __threadfence();
    __syncthreads();
    if (tid == 0) *s_isl = (atomicAdd(&d_done, 1) == NPB - 1);
    __syncthreads();
    if (!*s_isl) return;
    __threadfence();

    int*    sh    = (int*)sm;            // overlay on drained buffers
    double* shd   = (double*)(sm + 256);
    int*    s_nfb = (int*)(sm + OFF_NFB);
    int*    s_fbr = (int*)(sm + OFF_FBR);
    double* s_fin = (double*)(sm + OFF_FIN);

    // per-row selection. fast path: num_neg >= #negatives -> row sum = all ce.
    if (tid == 0) *s_nfb = 0;
    __syncthreads();
    if (tid < BB) {
        int npb = d_numpos[tid];
        long k3 = 3L * (long)npb;
        int k = (k3 < (long)(PP - 1)) ? (int)k3 : (PP - 1);
        int nneg = PP - npb;
        if (k >= nneg)      d_rowC[tid] = d_ce_all[tid];
        else if (k <= 0)    d_rowC[tid] = d_ce_pos[tid];
        else { int s = atomicAdd(s_nfb, 1); s_fbr[s] = tid; }
    }
    __syncthreads();

    // exact fallback (never triggered on this data): recompute ce for the row,
    // then bit-bisection for the k-th largest negative ce.
    const int nfbv = *s_nfb;
    for (int fi = 0; fi < nfbv; ++fi) {
        int bb = s_fbr[fi];
        long rb = (long)bb * PP;
        for (int i = warp; i < PP; i += 8) {
            const long cb = (rb + i) * CC;
            float v0 = conf[cb + lane];
            float v1 = conf[cb + lane + 32];
            float v2 = (lane < CC - 64) ? conf[cb + lane + 64] : 0.f;
            float s = __expf(v0) + __expf(v1);
            if (lane < CC - 64) s += __expf(v2);
            #pragma unroll
            for (int o = 16; o; o >>= 1) s += __shfl_xor_sync(0xffffffffu, s, o);
            int t = conf_t[rb + i];
            float cand = (t < 32) ? v0 : (t < 64) ? v1 : v2;
            float gath = __shfl_sync(0xffffffffu, cand, t & 31);
            if (lane == 0) d_ce_row[i] = __logf(s) - gath;
        }
        __syncthreads();
        int npb = d_numpos[bb];
        long k3 = 3L * (long)npb;
        int k = (k3 < (long)(PP - 1)) ? (int)k3 : (PP - 1);
        unsigned lo = 0u, hi = 0x7f800000u;
        while (lo < hi) {
            unsigned mid = lo + (hi - lo + 1u) / 2u;
            int c = 0;
            for (int i = tid; i < PP; i += TPB)
                if (conf_t[rb + i] == 0 &&
                    __float_as_uint(fmaxf(d_ce_row[i], 0.f)) >= mid) c++;
            sh[tid] = c; __syncthreads();
            for (int s = TPB/2; s; s >>= 1) { if (tid < s) sh[tid] += sh[tid + s]; __syncthreads(); }
            int tot = sh[0]; __syncthreads();
            if (tot >= k) lo = mid; else hi = mid - 1u;
        }
        int c = 0; double su = 0.0;
        for (int i = tid; i < PP; i += TPB) {
            if (conf_t[rb + i] == 0) {
                float v = d_ce_row[i];
                if (__float_as_uint(fmaxf(v, 0.f)) > lo) { c++; su += (double)v; }
            }
        }
        sh[tid] = c; shd[tid] = su; __syncthreads();
        for (int s = TPB/2; s; s >>= 1) {
            if (tid < s) { sh[tid] += sh[tid + s]; shd[tid] += shd[tid + s]; }
            __syncthreads();
        }
        if (tid == 0)
            d_rowC[bb] = d_ce_pos[bb] + shd[0] + (double)(k - sh[0]) * (double)__uint_as_float(lo);
        __syncthreads();
    }

    // ---- finalize (parallel) ----
    double n = (tid < BB) ? (double)d_numpos[tid] : 0.0;
    double c = (tid < BB) ? d_rowC[tid] : 0.0;
    if (tid < 64) {
        #pragma unroll
        for (int o = 16; o; o >>= 1) {
            n += __shfl_xor_sync(0xffffffffu, n, o);
            c += __shfl_xor_sync(0xffffffffu, c, o);
        }
        if (lane == 0) { s_fin[(tid >> 5) * 2] = n; s_fin[(tid >> 5) * 2 + 1] = c; }
    }
    __syncthreads();
    if (tid == 0) {
        double N  = s_fin[0] + s_fin[2];
        double Cc = s_fin[1] + s_fin[3];
        out[0] = (float)(d_loss_l / N);
        out[1] = (float)(Cc / N);
        out[2] = (float)(d_loss_fc / N);
    }

    // ---- self-reset device state for the next (graph-replayed) launch ----
    __syncthreads();
    if (tid < BB) {
        d_ce_all[tid] = 0.0; d_ce_pos[tid] = 0.0;
        d_numpos[tid] = 0;   d_rowC[tid]   = 0.0;
    }
    if (tid == 0) { d_loss_l = 0.0; d_loss_fc = 0.0; d_done = 0; }
}

extern "C" void kernel_launch(void* const* d_in, const int* in_sizes, int n_in,
                              void* d_out, int out_size) {
    const float* loc_data = (const float*)d_in[0];
    const float* conf     = (const float*)d_in[1];
    const float* fc_data  = (const float*)d_in[2];
    const float* loc_t    = (const float*)d_in[3];
    const float* fc_t     = (const float*)d_in[4];
    const int*   conf_t   = (const int*)d_in[5];

    cudaFuncSetAttribute(k_fused, cudaFuncAttributeMaxDynamicSharedMemorySize, SMEM_BYTES);
    k_fused<<<NPB, TPB, SMEM_BYTES>>>(loc_data, conf, fc_data, loc_t, fc_t, conf_t, (float*)d_out);
}